// round 2
// baseline (speedup 1.0000x reference)
#include <cuda_runtime.h>
#include <cstdint>

// Problem constants
constexpr int B  = 8;
constexpr int C  = 19;
constexpr int H  = 320;
constexpr int W  = 2048;
constexpr int HH_OFF = 10;   // lab slice rows 10:20
constexpr int HH_N  = 10;
constexpr int WW   = 128;    // 2048/16
constexpr int P    = HH_N * WW;  // 1280
constexpr long long NE = (long long)B * P * P; // elements per output tensor

// Scratch (no allocation allowed -> __device__ globals)
__device__ float g_sums[B * HH_N * WW * C];   // block sums per (b,hh,ww,c)
__device__ int   g_lab[B * P];                // argmax labels

// ---------------------------------------------------------------------------
// K1: per (b, hh, c) block computes 128 block-sums (one per ww).
// 256 threads; each thread streams 2 float4 per row over 16 rows.
// unroll 8 -> 16 LDG.128 outstanding per thread for max MLP; __ldcs since
// label is touched exactly once (keep L2 clean).
// ---------------------------------------------------------------------------
__global__ __launch_bounds__(256) void pool_sum_kernel(const float* __restrict__ label)
{
    const int c  = blockIdx.x;   // 0..18
    const int hh = blockIdx.y;   // 0..9
    const int b  = blockIdx.z;   // 0..7
    const int t  = threadIdx.x;  // 0..255

    const int h0 = (HH_OFF + hh) * 16;  // 160..304
    const float4* base = reinterpret_cast<const float4*>(
        label + (((size_t)b * C + c) * H + h0) * W);
    const int row_f4 = W / 4; // 512

    float acc0 = 0.f, acc1 = 0.f;
#pragma unroll 8
    for (int r = 0; r < 16; r++) {
        float4 v0 = __ldcs(base + (size_t)r * row_f4 + t);
        float4 v1 = __ldcs(base + (size_t)r * row_f4 + t + 256);
        acc0 += (v0.x + v0.y) + (v0.z + v0.w);
        acc1 += (v1.x + v1.y) + (v1.z + v1.w);
    }
    // Reduce across the 4 lanes sharing one ww (lanes 4k..4k+3)
    acc0 += __shfl_xor_sync(0xffffffffu, acc0, 1);
    acc0 += __shfl_xor_sync(0xffffffffu, acc0, 2);
    acc1 += __shfl_xor_sync(0xffffffffu, acc1, 1);
    acc1 += __shfl_xor_sync(0xffffffffu, acc1, 2);

    if ((t & 3) == 0) {
        const int ww0 = t >> 2;       // 0..63
        const int ww1 = ww0 + 64;     // 64..127
        const size_t rowbase = ((size_t)(b * HH_N + hh) * WW);
        g_sums[(rowbase + ww0) * C + c] = acc0;
        g_sums[(rowbase + ww1) * C + c] = acc1;
    }
}

// ---------------------------------------------------------------------------
// K2: argmax over 19 channels per pooled position -> g_lab. Tiny; g_sums is
// L2-resident (778 KB). Strict '>' == jnp.argmax first-occurrence tie-break.
// ---------------------------------------------------------------------------
__global__ __launch_bounds__(256) void argmax_kernel()
{
    const int idx = blockIdx.x * 256 + threadIdx.x;
    if (idx >= B * P) return;
    const float* s = g_sums + (size_t)idx * C;
    float best = s[0];
    int bi = 0;
#pragma unroll
    for (int c = 1; c < C; c++) {
        float v = s[c];
        if (v > best) { best = v; bi = c; }
    }
    g_lab[idx] = bi;
}

// ---------------------------------------------------------------------------
// K3: per (b,row i): mask-edit energy row, softmax, write e and attention_map.
// 320 threads; one float4 per thread (P=1280). Streaming loads + stores.
// ---------------------------------------------------------------------------
__global__ __launch_bounds__(320) void attn_kernel(const float* __restrict__ energy,
                                                   float* __restrict__ out)
{
    const int i = blockIdx.x;   // 0..1279
    const int b = blockIdx.y;   // 0..7
    const int t = threadIdx.x;  // 0..319
    const int wid = t >> 5;     // 0..9
    const int lid = t & 31;

    __shared__ int   lab_s[P];
    __shared__ float red_max[10];
    __shared__ float red_sum[10];

    // Load labels: 320 threads x int4 = 1280 ints
    const int4* labrow4 = reinterpret_cast<const int4*>(g_lab + b * P);
    reinterpret_cast<int4*>(lab_s)[t] = labrow4[t];
    __syncthreads();

    const int li = lab_s[i];
    const float4* erow = reinterpret_cast<const float4*>(energy + ((size_t)b * P + i) * P);

    float4 en = __ldcs(erow + t);
    const int4 lj = reinterpret_cast<const int4*>(lab_s)[t];

    float4 ev;
    ev.x = (lj.x == li) ? (en.x < 0.f ? 0.5f : en.x) : (en.x > 0.f ? -0.5f : en.x);
    ev.y = (lj.y == li) ? (en.y < 0.f ? 0.5f : en.y) : (en.y > 0.f ? -0.5f : en.y);
    ev.z = (lj.z == li) ? (en.z < 0.f ? 0.5f : en.z) : (en.z > 0.f ? -0.5f : en.z);
    ev.w = (lj.w == li) ? (en.w < 0.f ? 0.5f : en.w) : (en.w > 0.f ? -0.5f : en.w);

    float m = fmaxf(fmaxf(ev.x, ev.y), fmaxf(ev.z, ev.w));
#pragma unroll
    for (int o = 16; o > 0; o >>= 1) m = fmaxf(m, __shfl_xor_sync(0xffffffffu, m, o));
    if (lid == 0) red_max[wid] = m;
    __syncthreads();
    float bm = red_max[0];
#pragma unroll
    for (int w = 1; w < 10; w++) bm = fmaxf(bm, red_max[w]);

    float4 ex;
    ex.x = __expf(ev.x - bm);
    ex.y = __expf(ev.y - bm);
    ex.z = __expf(ev.z - bm);
    ex.w = __expf(ev.w - bm);
    float s = (ex.x + ex.y) + (ex.z + ex.w);
#pragma unroll
    for (int o = 16; o > 0; o >>= 1) s += __shfl_xor_sync(0xffffffffu, s, o);
    if (lid == 0) red_sum[wid] = s;
    __syncthreads();
    float tot = red_sum[0];
#pragma unroll
    for (int w = 1; w < 10; w++) tot += red_sum[w];
    const float inv = 1.f / tot;

    float4 am;
    am.x = ex.x * inv; am.y = ex.y * inv; am.z = ex.z * inv; am.w = ex.w * inv;

    float4* eout = reinterpret_cast<float4*>(out + ((size_t)b * P + i) * P);
    float4* aout = reinterpret_cast<float4*>(out + NE + ((size_t)b * P + i) * P);
    __stcs(eout + t, ev);
    __stcs(aout + t, am);
}

extern "C" void kernel_launch(void* const* d_in, const int* in_sizes, int n_in,
                              void* d_out, int out_size)
{
    const float* label  = (const float*)d_in[0];  // [8,19,320,2048] f32
    const float* energy = (const float*)d_in[1];  // [8,1280,1280]  f32
    float* out = (float*)d_out;                   // [2 * 8*1280*1280] f32 (e, attn)

    (void)in_sizes; (void)n_in; (void)out_size;

    dim3 g1(C, HH_N, B);
    pool_sum_kernel<<<g1, 256>>>(label);

    argmax_kernel<<<(B * P + 255) / 256, 256>>>();

    dim3 g3(P, B);
    attn_kernel<<<g3, 320>>>(energy, out);
}

// round 3
// speedup vs baseline: 1.0069x; 1.0069x over previous
#include <cuda_runtime.h>
#include <cstdint>

// Problem constants
constexpr int B  = 8;
constexpr int C  = 19;
constexpr int H  = 320;
constexpr int W  = 2048;
constexpr int HH_OFF = 10;   // lab slice rows 10:20
constexpr int HH_N  = 10;
constexpr int WW   = 128;    // 2048/16
constexpr int P    = HH_N * WW;  // 1280
constexpr long long NE = (long long)B * P * P;

constexpr int WCHUNK = 256;        // label columns per pool block
constexpr int NWCH   = W / WCHUNK; // 8
constexpr int ROWS   = 8;          // energy rows per attn block

__device__ int g_lab[B * P];       // argmax labels (only scratch needed now)

// ---------------------------------------------------------------------------
// K1 (fused pool + argmax): block per (wchunk, hh, b). 256 threads.
// Each block covers 16 ww positions x 19 channels: sums 16x16 blocks into
// smem, then argmaxes over channels and writes g_lab directly.
// Thread layout: f = t%64 is the float4 column index within the chunk
// (ww_local = f/4), cg = t/64 picks one of 4 channels per outer iteration.
// ---------------------------------------------------------------------------
__global__ __launch_bounds__(256) void pool_argmax_kernel(const float* __restrict__ label)
{
    const int wc = blockIdx.x;   // 0..7
    const int hh = blockIdx.y;   // 0..9
    const int b  = blockIdx.z;   // 0..7
    const int t  = threadIdx.x;
    const int f  = t & 63;       // 0..63 float4 within chunk
    const int cg = t >> 6;       // 0..3

    __shared__ float ssum[C][17];  // [channel][ww_local], padded

    const int h0 = (HH_OFF + hh) * 16;
    const int row_f4 = W / 4;    // 512

#pragma unroll
    for (int c4 = 0; c4 < 5; c4++) {
        const int c = c4 * 4 + cg;
        float acc = 0.f;
        if (c < C) {
            const float4* p = reinterpret_cast<const float4*>(
                label + (((size_t)b * C + c) * H + h0) * W + wc * WCHUNK) + f;
#pragma unroll
            for (int r = 0; r < 16; r++) {
                float4 v = __ldcs(p + (size_t)r * row_f4);
                acc += (v.x + v.y) + (v.z + v.w);
            }
        }
        // lanes 4k..4k+3 share one ww_local
        acc += __shfl_xor_sync(0xffffffffu, acc, 1);
        acc += __shfl_xor_sync(0xffffffffu, acc, 2);
        if (c < C && (t & 3) == 0) ssum[c][f >> 2] = acc;
    }
    __syncthreads();

    if (t < 16) {
        float best = ssum[0][t];
        int bi = 0;
#pragma unroll
        for (int c = 1; c < C; c++) {
            float v = ssum[c][t];
            if (v > best) { best = v; bi = c; }  // strict '>' = first-max tie-break
        }
        g_lab[(b * HH_N + hh) * WW + wc * 16 + t] = bi;
    }
}

// ---------------------------------------------------------------------------
// K2 (attn): block per (b, 8-row group). 320 threads, one float4 per thread
// per row. Labels loaded once per block. Softmax without max-shift (post-edit
// values bounded by ~|6|, exp safe in f32, softmax shift-invariant).
// ---------------------------------------------------------------------------
__global__ __launch_bounds__(320) void attn_kernel(const float* __restrict__ energy,
                                                   float* __restrict__ out)
{
    const int b  = blockIdx.y;
    const int i0 = blockIdx.x * ROWS;
    const int t  = threadIdx.x;   // 0..319
    const int wid = t >> 5;       // 0..9
    const int lid = t & 31;

    __shared__ int   lab_s[P];
    __shared__ float red_sum[10];

    reinterpret_cast<int4*>(lab_s)[t] =
        reinterpret_cast<const int4*>(g_lab + b * P)[t];
    __syncthreads();

    const int4 lj = reinterpret_cast<const int4*>(lab_s)[t];

    for (int ri = 0; ri < ROWS; ri++) {
        const int i = i0 + ri;
        const int li = lab_s[i];

        const float4* erow = reinterpret_cast<const float4*>(
            energy + ((size_t)b * P + i) * P);
        float4 en = __ldcs(erow + t);

        float4 ev;
        ev.x = (lj.x == li) ? (en.x < 0.f ? 0.5f : en.x) : (en.x > 0.f ? -0.5f : en.x);
        ev.y = (lj.y == li) ? (en.y < 0.f ? 0.5f : en.y) : (en.y > 0.f ? -0.5f : en.y);
        ev.z = (lj.z == li) ? (en.z < 0.f ? 0.5f : en.z) : (en.z > 0.f ? -0.5f : en.z);
        ev.w = (lj.w == li) ? (en.w < 0.f ? 0.5f : en.w) : (en.w > 0.f ? -0.5f : en.w);

        float4 ex;
        ex.x = __expf(ev.x);
        ex.y = __expf(ev.y);
        ex.z = __expf(ev.z);
        ex.w = __expf(ev.w);
        float s = (ex.x + ex.y) + (ex.z + ex.w);
#pragma unroll
        for (int o = 16; o > 0; o >>= 1) s += __shfl_xor_sync(0xffffffffu, s, o);

        __syncthreads();               // prev iteration's red_sum reads done
        if (lid == 0) red_sum[wid] = s;
        __syncthreads();

        float tot = red_sum[0];
#pragma unroll
        for (int w = 1; w < 10; w++) tot += red_sum[w];
        const float inv = 1.f / tot;

        float4 am;
        am.x = ex.x * inv; am.y = ex.y * inv; am.z = ex.z * inv; am.w = ex.w * inv;

        float4* eout = reinterpret_cast<float4*>(out + ((size_t)b * P + i) * P);
        float4* aout = reinterpret_cast<float4*>(out + NE + ((size_t)b * P + i) * P);
        __stcs(eout + t, ev);
        __stcs(aout + t, am);
    }
}

extern "C" void kernel_launch(void* const* d_in, const int* in_sizes, int n_in,
                              void* d_out, int out_size)
{
    const float* label  = (const float*)d_in[0];  // [8,19,320,2048] f32
    const float* energy = (const float*)d_in[1];  // [8,1280,1280]  f32
    float* out = (float*)d_out;                   // [2 * 8*1280*1280] f32 (e, attn)

    (void)in_sizes; (void)n_in; (void)out_size;

    dim3 g1(NWCH, HH_N, B);          // 640 blocks
    pool_argmax_kernel<<<g1, 256>>>(label);

    dim3 g2(P / ROWS, B);            // 1280 blocks
    attn_kernel<<<g2, 320>>>(energy, out);
}